// round 1
// baseline (speedup 1.0000x reference)
#include <cuda_runtime.h>
#include <math.h>

// Problem constants (from reference): x:(N,D,L), out:(N,D,K)
#define N_ 128
#define D_ 512
#define L_ 512
#define K_ 512
#define M_ (N_ * D_)   // 65536 GEMM rows

// Precomputed operands (static device globals: allocation-free scratch)
__device__ float g_w[D_ * L_];     // sigma-scaled Hann-family window, (D,L)
__device__ float g_cos[L_ * K_];   // cos basis, (L,K)
__device__ float g_sin[L_ * K_];   // sin basis, (L,K)

// ---------------------------------------------------------------------------
// Precompute: window w[d,l] = (a[d] - (1-a[d])cos(2pi l/(L-1))) * exp(sigma[d]/(L-1))
//             basis  cos/sin( (2pi/(L-1)) * l * k )
// Matches jax fp32 arithmetic: angle = fp32(2pi/511) * fp32(l*k), l*k < 2^24 exact.
// ---------------------------------------------------------------------------
__global__ void precompute_kernel(const float* __restrict__ a,
                                  const float* __restrict__ sigma) {
    const int idx = blockIdx.x * blockDim.x + threadIdx.x;
    const float c = (float)(6.283185307179586 / 511.0);  // 2*pi / (L-1)

    if (idx < L_ * K_) {
        const int l = idx / K_;
        const int k = idx - l * K_;
        float s, cc;
        sincosf(c * (float)(l * k), &s, &cc);
        g_cos[idx] = cc;
        g_sin[idx] = s;
    }
    if (idx < D_ * L_) {
        const int d = idx / L_;
        const int l = idx - d * L_;
        const float ad = a[d];
        const float w = ad - (1.0f - ad) * cosf(c * (float)l);
        g_w[idx] = w * expf(sigma[d] * (1.0f / 511.0f));
    }
}

// ---------------------------------------------------------------------------
// Fused dual-GEMM + magnitude:
//   out[row, k] = sqrt( (xw[row,:] . cos[:,k])^2 + (xw[row,:] . sin[:,k])^2 )
// where xw[row, l] = x[row, l] * g_w[row % D, l], row = n*D + d.
// BM=128, BN=64, BK=16; 256 threads; 8x4 micro-tile, two accumulator banks.
// ---------------------------------------------------------------------------
#define BM 128
#define BN 64
#define BK 16
#define TM 8
#define TN 4

__global__ __launch_bounds__(256, 2)
void spectro_gemm_kernel(const float* __restrict__ x, float* __restrict__ out) {
    __shared__ float As[BK][BM];   // A tile, k-major (stride-1 in m for compute reads)
    __shared__ float Bc[BK][BN];
    __shared__ float Bs[BK][BN];

    const int row0 = blockIdx.y * BM;
    const int col0 = blockIdx.x * BN;
    const int tid  = threadIdx.x;

    // A-load mapping: 2 passes of 64 rows x 16 cols (float4 per thread per pass)
    const int ar = tid >> 2;            // 0..63
    const int ac = (tid & 3) << 2;      // 0,4,8,12
    // B-load mapping: 16 rows x 64 cols (float4 per thread per matrix)
    const int br = tid >> 4;            // 0..15
    const int bcol = (tid & 15) << 2;   // 0..60

    // Compute mapping: 16x16 thread grid
    const int tx = tid & 15;            // column group -> n0
    const int ty = tid >> 4;            // row group    -> m0
    const int m0 = ty * TM;
    const int n0 = tx * TN;

    float accR[TM][TN];
    float accI[TM][TN];
#pragma unroll
    for (int i = 0; i < TM; ++i)
#pragma unroll
        for (int j = 0; j < TN; ++j) { accR[i][j] = 0.0f; accI[i][j] = 0.0f; }

    for (int kt = 0; kt < L_; kt += BK) {
        // ---- load A tile (window fused) ----
#pragma unroll
        for (int half = 0; half < 2; ++half) {
            const int r   = ar + half * 64;
            const int row = row0 + r;
            const int d   = row & (D_ - 1);
            const float4 xv = *(const float4*)(x   + (size_t)row * L_ + kt + ac);
            const float4 wv = *(const float4*)(g_w + (size_t)d   * L_ + kt + ac);
            As[ac + 0][r] = xv.x * wv.x;
            As[ac + 1][r] = xv.y * wv.y;
            As[ac + 2][r] = xv.z * wv.z;
            As[ac + 3][r] = xv.w * wv.w;
        }
        // ---- load B tiles (cos & sin) ----
        {
            const size_t boff = (size_t)(kt + br) * K_ + col0 + bcol;
            *(float4*)&Bc[br][bcol] = *(const float4*)(g_cos + boff);
            *(float4*)&Bs[br][bcol] = *(const float4*)(g_sin + boff);
        }
        __syncthreads();

        // ---- compute ----
#pragma unroll
        for (int k = 0; k < BK; ++k) {
            float af[TM];
            const float4 a0 = *(const float4*)&As[k][m0];
            const float4 a1 = *(const float4*)&As[k][m0 + 4];
            af[0] = a0.x; af[1] = a0.y; af[2] = a0.z; af[3] = a0.w;
            af[4] = a1.x; af[5] = a1.y; af[6] = a1.z; af[7] = a1.w;
            const float4 bcv = *(const float4*)&Bc[k][n0];
            const float4 bsv = *(const float4*)&Bs[k][n0];
            const float bcf[TN] = {bcv.x, bcv.y, bcv.z, bcv.w};
            const float bsf[TN] = {bsv.x, bsv.y, bsv.z, bsv.w};
#pragma unroll
            for (int i = 0; i < TM; ++i) {
#pragma unroll
                for (int j = 0; j < TN; ++j) {
                    accR[i][j] = fmaf(af[i], bcf[j], accR[i][j]);
                    accI[i][j] = fmaf(af[i], bsf[j], accI[i][j]);
                }
            }
        }
        __syncthreads();
    }

    // ---- epilogue: magnitude, vectorized store ----
#pragma unroll
    for (int i = 0; i < TM; ++i) {
        const int row = row0 + m0 + i;
        float4 o;
        o.x = sqrtf(fmaf(accR[i][0], accR[i][0], accI[i][0] * accI[i][0]));
        o.y = sqrtf(fmaf(accR[i][1], accR[i][1], accI[i][1] * accI[i][1]));
        o.z = sqrtf(fmaf(accR[i][2], accR[i][2], accI[i][2] * accI[i][2]));
        o.w = sqrtf(fmaf(accR[i][3], accR[i][3], accI[i][3] * accI[i][3]));
        *(float4*)(out + (size_t)row * K_ + col0 + n0) = o;
    }
}

// ---------------------------------------------------------------------------
extern "C" void kernel_launch(void* const* d_in, const int* in_sizes, int n_in,
                              void* d_out, int out_size) {
    const float* x     = (const float*)d_in[0];  // (N, D, L) float32
    const float* a     = (const float*)d_in[1];  // (D,)      float32
    const float* sigma = (const float*)d_in[2];  // (D,)      float32
    float* out = (float*)d_out;                  // (N, D, K) float32

    // Precompute basis + window (covers max(L*K, D*L) = 262144 elements)
    precompute_kernel<<<(L_ * K_ + 255) / 256, 256>>>(a, sigma);

    // Fused dual-GEMM + magnitude
    dim3 grid(K_ / BN, M_ / BM);   // (8, 512)
    spectro_gemm_kernel<<<grid, 256>>>(x, out);
}